// round 8
// baseline (speedup 1.0000x reference)
#include <cuda_runtime.h>
#include <math_constants.h>

// Problem constants (NB, LQ, LK, DK, DV = 16, 384, 384, 64, 64)
#define NB 16
#define LQ 384
#define LK 384
#define DK 64
#define DV 64
#define QTA 8            // q-rows per block (384/8=48 -> 768 blocks)
#define INV_TEMP 0.125f  // 1 / TEMPERATURE, TEMPERATURE = 8.0

// Scratch for attn probabilities in case the harness output only holds `output`.
__device__ float g_attn_scratch[NB * LQ * LK];

// Dynamic smem layout:
//   qs4    : QTA*16 float4   (2 KB)
//   ks4    : LK*16  float4   (96 KB), XOR-swizzled columns
//   scores : QTA*LK floats   (12 KB) — raw scores, then normalized probs
#define SMEM_K4_OFF  (QTA * 16)                     // float4 units
#define SMEM_SC_OFF  ((QTA * 16 + LK * 16) * 4)     // float units
#define FUSED_SMEM_BYTES ((QTA * 16 + LK * 16) * 16 + QTA * LK * 4)  // 112640

// ---------------------------------------------------------------------------
// Fused kernel.
// Phase 1 (R6-proven): stage q + full K[n] (coalesced, swizzle d4^(k&7)),
//   thread t computes scores for k-rows {t, t+128, t+256} vs 8 q-rows.
// Phase 2 (per-warp, no block syncs): warp w owns q-rows {w, w+4}:
//   softmax -> write probs to smem + attn to gmem -> immediately stream
//   rel_pos_v for that row (192 coalesced float4 loads per lane-pair layout),
//   fold halves with one shfl_xor(16), lanes 0..15 store the 64-float out row.
// Fusing hides the attn compute under the 604 MB DRAM stream (L2 had 45%
// headroom at DRAM=85%, so the K re-reads are absorbed by L2).
// ---------------------------------------------------------------------------
__global__ __launch_bounds__(128, 2)
void fused_kernel(const float* __restrict__ q,
                  const float* __restrict__ k,
                  const float* __restrict__ rpv,
                  float* __restrict__ out,
                  float* __restrict__ attn_ext)
{
    extern __shared__ float4 smem4[];
    float4* qs4    = smem4;                                       // [QTA][16]
    float4* ks4    = smem4 + SMEM_K4_OFF;                         // [LK][16] swz
    float*  scores = reinterpret_cast<float*>(smem4) + SMEM_SC_OFF; // [QTA][LK]

    float* attn = attn_ext ? attn_ext : g_attn_scratch;

    const int n   = blockIdx.y;
    const int q0  = blockIdx.x * QTA;
    const int tid = threadIdx.x;             // 0..127

    // ---- Phase 1a: stage q (128 float4) and K[n] (6144 float4), coalesced.
    {
        const float4* qsrc = reinterpret_cast<const float4*>(
            q + ((size_t)n * LQ + q0) * DK);
        qs4[tid] = qsrc[tid];

        const float4* ksrc = reinterpret_cast<const float4*>(
            k + (size_t)n * LK * DK);
#pragma unroll
        for (int i = 0; i < (LK * DK / 4) / 128; i++) {   // 48
            const int idx = tid + i * 128;
            const int kl  = idx >> 4;
            const int d4  = idx & 15;
            ks4[kl * 16 + (d4 ^ (kl & 7))] = ksrc[idx];
        }
    }
    __syncthreads();

    // ---- Phase 1b: scores, 3 k-rows x 8 q-rows per thread.
    {
        const int sw = tid & 7;              // (tid+128j)&7 == tid&7
        float acc[3][QTA];
#pragma unroll
        for (int j = 0; j < 3; j++)
#pragma unroll
            for (int qq = 0; qq < QTA; qq++) acc[j][qq] = 0.0f;

#pragma unroll
        for (int i = 0; i < DK / 4; i++) {
            float4 kv[3];
#pragma unroll
            for (int j = 0; j < 3; j++)
                kv[j] = ks4[(tid + j * 128) * 16 + (i ^ sw)];   // conflict-free
#pragma unroll
            for (int qq = 0; qq < QTA; qq++) {
                const float4 a = qs4[qq * 16 + i];              // broadcast
#pragma unroll
                for (int j = 0; j < 3; j++) {
                    acc[j][qq] += a.x * kv[j].x + a.y * kv[j].y
                                + a.z * kv[j].z + a.w * kv[j].w;
                }
            }
        }
#pragma unroll
        for (int j = 0; j < 3; j++)
#pragma unroll
            for (int qq = 0; qq < QTA; qq++)
                scores[qq * LK + (tid + j * 128)] = acc[j][qq] * INV_TEMP;
    }
    __syncthreads();

    // ---- Phase 2: per-warp softmax + rel_pos_v stream. No block syncs.
    const int warp = tid >> 5;
    const int lane = tid & 31;
    const int d4   = lane & 15;   // float4 column of the out/value row
    const int kh   = lane >> 4;   // k-half (0/1); lane pair covers k = kh + 2i

#pragma unroll
    for (int qq = warp; qq < QTA; qq += 4) {
        float* row = scores + qq * LK;

        // Softmax over 384 (12 elems per lane).
        float m = -CUDART_INF_F;
#pragma unroll
        for (int j = 0; j < LK / 32; j++) m = fmaxf(m, row[lane + j * 32]);
#pragma unroll
        for (int s = 16; s > 0; s >>= 1)
            m = fmaxf(m, __shfl_xor_sync(0xFFFFFFFFu, m, s));

        float e[LK / 32];
        float sum = 0.0f;
#pragma unroll
        for (int j = 0; j < LK / 32; j++) {
            e[j] = __expf(row[lane + j * 32] - m);
            sum += e[j];
        }
#pragma unroll
        for (int s = 16; s > 0; s >>= 1)
            sum += __shfl_xor_sync(0xFFFFFFFFu, sum, s);
        const float inv = 1.0f / sum;

        // Write probs back to smem (for the stream below) and attn to gmem.
        float* arow = attn + ((size_t)n * LQ + q0 + qq) * LK;
#pragma unroll
        for (int j = 0; j < LK / 32; j++) {
            const float p = e[j] * inv;
            row[lane + j * 32] = p;     // each lane rewrites its own slots
            arow[lane + j * 32] = p;
        }
        __syncwarp();                   // probs visible warp-wide

        // Stream rel_pos_v[n, q0+qq, :, :]: 6144 float4, 192 per lane.
        // kidx = kh + 2*i -> lanes 0-15 row 2i, lanes 16-31 row 2i+1:
        // each warp-LDG covers 512 contiguous bytes. Full coalescing.
        const float4* base = reinterpret_cast<const float4*>(
            rpv + ((size_t)n * LQ + q0 + qq) * LK * DV);

        float4 acc = make_float4(0.f, 0.f, 0.f, 0.f);
#pragma unroll 16
        for (int i = 0; i < LK / 2; i++) {      // 192
            const int kidx = kh + 2 * i;
            const float  a = row[kidx];
            const float4 v = base[kidx * (DV / 4) + d4];
            acc.x += a * v.x;
            acc.y += a * v.y;
            acc.z += a * v.z;
            acc.w += a * v.w;
        }

        // Fold the two k-halves (lane ^ 16 partner).
        acc.x += __shfl_xor_sync(0xFFFFFFFFu, acc.x, 16);
        acc.y += __shfl_xor_sync(0xFFFFFFFFu, acc.y, 16);
        acc.z += __shfl_xor_sync(0xFFFFFFFFu, acc.z, 16);
        acc.w += __shfl_xor_sync(0xFFFFFFFFu, acc.w, 16);

        if (lane < 16) {
            float4* orow = reinterpret_cast<float4*>(
                out + ((size_t)n * LQ + q0 + qq) * DV);
            orow[lane] = acc;
        }
    }
}

// ---------------------------------------------------------------------------
// Launch. Inputs (metadata order) = q, k, v, rel_pos, rel_pos_v.
// v and rel_pos are unused by the reference — never touched.
// Output layout: [output (NB*LQ*DV) | attn (NB*LQ*LK)] when out_size covers
// both (branch taken and passing since R3); otherwise attn -> scratch.
// ---------------------------------------------------------------------------
extern "C" void kernel_launch(void* const* d_in, const int* in_sizes, int n_in,
                              void* d_out, int out_size)
{
    const float* q   = (const float*)d_in[0];
    const float* k   = (const float*)d_in[1];
    const float* rpv = (const float*)d_in[4];
    float* out = (float*)d_out;

    const long long out_elems  = (long long)NB * LQ * DV;   // 393216
    const long long attn_elems = (long long)NB * LQ * LK;   // 2359296

    float* attn_ext = nullptr;  // null -> kernel falls back to g_attn_scratch
    if ((long long)out_size >= out_elems + attn_elems) {
        attn_ext = out + out_elems;
    }

    static int smem_attr_set = 0;
    if (!smem_attr_set) {
        cudaFuncSetAttribute(fused_kernel,
                             cudaFuncAttributeMaxDynamicSharedMemorySize,
                             FUSED_SMEM_BYTES);
        smem_attr_set = 1;
    }

    dim3 grid(LQ / QTA, NB);
    fused_kernel<<<grid, 128, FUSED_SMEM_BYTES>>>(q, k, rpv, out, attn_ext);
}

// round 9
// speedup vs baseline: 1.3334x; 1.3334x over previous
#include <cuda_runtime.h>
#include <math_constants.h>

// Problem constants (NB, LQ, LK, DK, DV = 16, 384, 384, 64, 64)
#define NB 16
#define LQ 384
#define LK 384
#define DK 64
#define DV 64
#define INV_TEMP 0.125f  // 1 / TEMPERATURE, TEMPERATURE = 8.0

// Scratch for attn probabilities in case the harness output only holds `output`.
__device__ float g_attn_scratch[NB * LQ * LK];

// ---------------------------------------------------------------------------
// Single fused kernel, one block per (n,q), 256 threads — the PROVEN
// out_kernel geometry (occ 8, ~31 regs, 85% DRAM) with a cheap attn prologue.
//
// Prologue (phase A): this block's attn row computed in-place.
//   q-row staged in smem. Half-warp h reads K-row (h + 16*i) as 16
//   consecutive float4s -> each warp LDG covers 512 contiguous bytes (fully
//   coalesced, L2-resident: K[n] is 96 KB, re-read by 384 blocks -> 576 MB
//   of pure-L2 traffic; measured LTS headroom 55% -> ~12 TB/s cap absorbs it).
//   dot4 + 4 shfl_xor folds the 16 lanes; 24 passes cover 384 rows.
// Phase B: block softmax over the 384 scores (2 warp+smem reductions),
//   probs written to smem and to the attn output (coalesced).
// Phase C: byte-identical rel_pos_v streaming loop from the 85%-DRAM kernel.
//
// This deletes the separate ~25us attn kernel and its gmem roundtrip; the
// kernel becomes jointly DRAM/LTS-bound at ~97us floor.
// ---------------------------------------------------------------------------
__global__ __launch_bounds__(256, 8)
void fused_kernel(const float* __restrict__ q,
                  const float* __restrict__ k,
                  const float* __restrict__ rpv,
                  float* __restrict__ out,
                  float* __restrict__ attn_ext)
{
    __shared__ float4 sq4[DK / 4];   // q row, 256 B
    __shared__ float  sa[LK];        // scores -> probs, 1.5 KB
    __shared__ float4 rbuf[256];     // reduction buffer, 4 KB
    __shared__ float  red[16];       // block-reduction partials

    float* attn = attn_ext ? attn_ext : g_attn_scratch;

    const int nq   = blockIdx.x;           // n*LQ + q
    const int n    = nq / LQ;
    const int tid  = threadIdx.x;
    const int lane = tid & 31;
    const int warp = tid >> 5;

    // ---- Phase A: attn scores for this (n,q) row. ----
    if (tid < DK / 4) {
        sq4[tid] = reinterpret_cast<const float4*>(q + (size_t)nq * DK)[tid];
    }
    __syncthreads();

    {
        const int half = tid >> 4;         // 0..15: half-warp id
        const int d4   = tid & 15;         // float4 column within the row
        const float4 qv = sq4[d4];

        const float4* kbase = reinterpret_cast<const float4*>(
            k + (size_t)n * LK * DK);

#pragma unroll
        for (int i = 0; i < LK / 16; i++) {          // 24 passes
            const int krow = half + 16 * i;
            // threads 0-15 cover row `half` float4s 0-15: 256B contiguous;
            // full warp covers 512 contiguous bytes. L2-hot.
            const float4 kv = kbase[krow * (DK / 4) + d4];
            float p = qv.x * kv.x + qv.y * kv.y + qv.z * kv.z + qv.w * kv.w;
            // Fold the 16 lanes of this half-warp.
            p += __shfl_xor_sync(0xFFFFFFFFu, p, 8);
            p += __shfl_xor_sync(0xFFFFFFFFu, p, 4);
            p += __shfl_xor_sync(0xFFFFFFFFu, p, 2);
            p += __shfl_xor_sync(0xFFFFFFFFu, p, 1);
            if (d4 == 0) sa[krow] = p * INV_TEMP;
        }
    }
    __syncthreads();

    // ---- Phase B: softmax over sa[0..383] with 256 threads. ----
    {
        const float v1 = sa[tid];
        const float v2 = (tid < LK - 256) ? sa[tid + 256] : -CUDART_INF_F;

        // Block max.
        float m = fmaxf(v1, v2);
#pragma unroll
        for (int s = 16; s > 0; s >>= 1)
            m = fmaxf(m, __shfl_xor_sync(0xFFFFFFFFu, m, s));
        if (lane == 0) red[warp] = m;
        __syncthreads();
        if (tid < 32) {
            float t = (lane < 8) ? red[lane] : -CUDART_INF_F;
#pragma unroll
            for (int s = 4; s > 0; s >>= 1)
                t = fmaxf(t, __shfl_xor_sync(0xFFFFFFFFu, t, s));
            if (lane == 0) red[0] = t;
        }
        __syncthreads();
        const float mm = red[0];

        // exp + block sum.
        const float e1 = __expf(v1 - mm);
        const float e2 = (tid < LK - 256) ? __expf(v2 - mm) : 0.0f;
        float s = e1 + e2;
#pragma unroll
        for (int sh = 16; sh > 0; sh >>= 1)
            s += __shfl_xor_sync(0xFFFFFFFFu, s, sh);
        if (lane == 0) red[8 + warp] = s;
        __syncthreads();
        if (tid < 32) {
            float t = (lane < 8) ? red[8 + lane] : 0.0f;
#pragma unroll
            for (int sh = 4; sh > 0; sh >>= 1)
                t += __shfl_xor_sync(0xFFFFFFFFu, t, sh);
            if (lane == 0) red[8] = t;
        }
        __syncthreads();
        const float inv = 1.0f / red[8];

        // Probs to smem + attn output (coalesced).
        float* arow = attn + (size_t)nq * LK;
        const float p1 = e1 * inv;
        sa[tid]  = p1;
        arow[tid] = p1;
        if (tid < LK - 256) {
            const float p2 = e2 * inv;
            sa[tid + 256]  = p2;
            arow[tid + 256] = p2;
        }
    }
    __syncthreads();

    // ---- Phase C: stream rel_pos_v (unchanged from the 85%-DRAM kernel). ----
    const int d4 = tid & 15;   // float4 column (d = 4*d4 .. 4*d4+3)
    const int kk = tid >> 4;   // k-slice start (k = kk, kk+16, ...)

    const float4* base = reinterpret_cast<const float4*>(
        rpv + (size_t)nq * LK * DV);

    float4 acc = make_float4(0.f, 0.f, 0.f, 0.f);
#pragma unroll
    for (int i = 0; i < LK / 16; i++) {          // 24 iterations
        const int kidx = kk + i * 16;
        const float  a = sa[kidx];
        const float4 v = base[kidx * (DV / 4) + d4];
        acc.x += a * v.x;
        acc.y += a * v.y;
        acc.z += a * v.z;
        acc.w += a * v.w;
    }

    rbuf[tid] = acc;
    __syncthreads();

#pragma unroll
    for (int s = 128; s >= 16; s >>= 1) {
        if (tid < s) {
            float4 a = rbuf[tid];
            float4 b = rbuf[tid + s];
            a.x += b.x; a.y += b.y; a.z += b.z; a.w += b.w;
            rbuf[tid] = a;
        }
        __syncthreads();
    }

    if (tid < DV) {
        out[(size_t)nq * DV + tid] = reinterpret_cast<const float*>(rbuf)[tid];
    }
}

// ---------------------------------------------------------------------------
// Launch. Inputs (metadata order) = q, k, v, rel_pos, rel_pos_v.
// v and rel_pos are unused by the reference — never touched.
// Output layout: [output (NB*LQ*DV) | attn (NB*LQ*LK)] when out_size covers
// both (branch taken and passing since R3); otherwise attn -> scratch.
// ---------------------------------------------------------------------------
extern "C" void kernel_launch(void* const* d_in, const int* in_sizes, int n_in,
                              void* d_out, int out_size)
{
    const float* q   = (const float*)d_in[0];
    const float* k   = (const float*)d_in[1];
    const float* rpv = (const float*)d_in[4];
    float* out = (float*)d_out;

    const long long out_elems  = (long long)NB * LQ * DV;   // 393216
    const long long attn_elems = (long long)NB * LQ * LK;   // 2359296

    float* attn_ext = nullptr;  // null -> kernel falls back to g_attn_scratch
    if ((long long)out_size >= out_elems + attn_elems) {
        attn_ext = out + out_elems;
    }

    fused_kernel<<<NB * LQ, 256>>>(q, k, rpv, out, attn_ext);
}